// round 1
// baseline (speedup 1.0000x reference)
#include <cuda_runtime.h>
#include <math.h>

#define Bb   8
#define Cc   256
#define Hh   64
#define Ww   64
#define Oo   256
#define K2c  9
#define HW   4096
#define OCOFF 27
#define KTOT (Cc * K2c)     /* 2304 */
#define NTOT (Bb * HW)      /* 32768 */

// Scratch (allocation-free rule: __device__ globals)
__device__ float g_om[Bb * OCOFF * HW];          // off_y | off_x | sigmoid(mask)
__device__ float g_cols[(size_t)KTOT * NTOT];    // [c*9+k][b*4096+hw], ~302 MB

// ---------------------------------------------------------------------------
// Kernel A: 3x3 offset conv (27 output channels), sigmoid applied to mask chans
// one 64-thread block per (b, oc, h) row
// ---------------------------------------------------------------------------
__global__ void offset_conv_kernel(const float* __restrict__ x,
                                   const float* __restrict__ w_off,
                                   const float* __restrict__ b_off) {
    int blk = blockIdx.x;
    int h   = blk % Hh;
    int oc  = (blk / Hh) % OCOFF;
    int b   = blk / (Hh * OCOFF);
    int w   = threadIdx.x;

    float acc = b_off[oc];
    const float* xb   = x + (size_t)b * Cc * HW;
    const float* wrow = w_off + (size_t)oc * Cc * 9;

    for (int c = 0; c < Cc; ++c) {
        const float* xc = xb + (size_t)c * HW;
        const float* wk = wrow + c * 9;
        float wr[9];
#pragma unroll
        for (int i = 0; i < 9; ++i) wr[i] = __ldg(&wk[i]);

#pragma unroll
        for (int dy = 0; dy < 3; ++dy) {
            int yy = h - 1 + dy;
            if (yy < 0 || yy >= Hh) continue;
            const float* xr = xc + yy * Ww;
#pragma unroll
            for (int dx = 0; dx < 3; ++dx) {
                int xx = w - 1 + dx;
                if (xx < 0 || xx >= Ww) continue;
                acc += xr[xx] * wr[dy * 3 + dx];
            }
        }
    }
    if (oc >= 2 * K2c) acc = 1.0f / (1.0f + expf(-acc));
    g_om[((size_t)(b * OCOFF + oc)) * HW + h * Ww + w] = acc;
}

// ---------------------------------------------------------------------------
// Kernel B: build cols[c*9+k][b*4096+hw] = mask * bilinear(x_b_c, py, px)
// ---------------------------------------------------------------------------
__global__ void build_cols_kernel(const float* __restrict__ x) {
    size_t t = (size_t)blockIdx.x * blockDim.x + threadIdx.x;
    if (t >= (size_t)KTOT * NTOT) return;

    int hw   = (int)(t & (HW - 1));
    int rest = (int)(t >> 12);
    int b    = rest & 7;
    int ck   = rest >> 3;
    int k    = ck % 9;
    int c    = ck / 9;

    int h = hw >> 6;
    int w = hw & 63;

    const float* omb = g_om + (size_t)b * OCOFF * HW;
    float oy = omb[(size_t)k * HW + hw];
    float ox = omb[(size_t)(K2c + k) * HW + hw];
    float m  = omb[(size_t)(2 * K2c + k) * HW + hw];

    float py = (float)(h - 1 + k / 3) + oy;
    float px = (float)(w - 1 + k % 3) + ox;

    float y0f = floorf(py), x0f = floorf(px);
    float wy1 = py - y0f,   wx1 = px - x0f;
    int y0 = (int)y0f, x0 = (int)x0f;

    const float* xc = x + ((size_t)b * Cc + c) * HW;

    float v00 = 0.f, v01 = 0.f, v10 = 0.f, v11 = 0.f;
    bool yv0 = (y0 >= 0) & (y0 < Hh);
    bool yv1 = (y0 + 1 >= 0) & (y0 + 1 < Hh);
    bool xv0 = (x0 >= 0) & (x0 < Ww);
    bool xv1 = (x0 + 1 >= 0) & (x0 + 1 < Ww);
    if (yv0 & xv0) v00 = xc[y0 * Ww + x0];
    if (yv0 & xv1) v01 = xc[y0 * Ww + x0 + 1];
    if (yv1 & xv0) v10 = xc[(y0 + 1) * Ww + x0];
    if (yv1 & xv1) v11 = xc[(y0 + 1) * Ww + x0 + 1];

    float val = v00 * (1.f - wy1) * (1.f - wx1)
              + v01 * (1.f - wy1) * wx1
              + v10 * wy1 * (1.f - wx1)
              + v11 * wy1 * wx1;

    g_cols[t] = val * m;
}

// ---------------------------------------------------------------------------
// Kernel C: SGEMM out[o][n] = sum_K w3[o][K] * cols[K][n], fused bias+BN+ReLU
// 128x128x16 tiles, 256 threads, 8x8 microtile
// ---------------------------------------------------------------------------
__global__ __launch_bounds__(256)
void gemm_epilogue_kernel(const float* __restrict__ Amat,   // weight [O][2304]
                          const float* __restrict__ bias,
                          const float* __restrict__ gamma,
                          const float* __restrict__ beta,
                          const float* __restrict__ rmean,
                          const float* __restrict__ rvar,
                          float* __restrict__ out) {
    __shared__ float As[16][128];
    __shared__ float Bs[16][128];

    int bm = blockIdx.y * 128;
    int bn = blockIdx.x * 128;
    int tid = threadIdx.x;
    int tx = tid & 15;       // N direction
    int ty = tid >> 4;       // M direction

    float acc[8][8];
#pragma unroll
    for (int i = 0; i < 8; ++i)
#pragma unroll
        for (int j = 0; j < 8; ++j) acc[i][j] = 0.f;

    const float* Bmat = g_cols;

    for (int k0 = 0; k0 < KTOT; k0 += 16) {
        // A tile: 128 rows x 16 k, stored transposed
#pragma unroll
        for (int i = 0; i < 8; ++i) {
            int idx = tid + i * 256;        // 0..2047
            int m   = idx >> 4;
            int kk  = idx & 15;
            As[kk][m] = Amat[(size_t)(bm + m) * KTOT + k0 + kk];
        }
        // B tile: 16 k x 128 n, coalesced
#pragma unroll
        for (int i = 0; i < 8; ++i) {
            int idx = tid + i * 256;
            int kk  = idx >> 7;
            int n   = idx & 127;
            Bs[kk][n] = Bmat[(size_t)(k0 + kk) * NTOT + bn + n];
        }
        __syncthreads();

#pragma unroll
        for (int kk = 0; kk < 16; ++kk) {
            float a[8], bb[8];
#pragma unroll
            for (int i = 0; i < 8; ++i) a[i]  = As[kk][ty * 8 + i];
#pragma unroll
            for (int j = 0; j < 8; ++j) bb[j] = Bs[kk][tx * 8 + j];
#pragma unroll
            for (int i = 0; i < 8; ++i)
#pragma unroll
                for (int j = 0; j < 8; ++j)
                    acc[i][j] = fmaf(a[i], bb[j], acc[i][j]);
        }
        __syncthreads();
    }

    // epilogue: (acc + bias)*inv + (beta - mean*inv), relu
    float scale[8], shift[8];
#pragma unroll
    for (int i = 0; i < 8; ++i) {
        int o = bm + ty * 8 + i;
        float inv = gamma[o] * rsqrtf(rvar[o] + 1e-5f);
        scale[i] = inv;
        shift[i] = beta[o] - rmean[o] * inv + bias[o] * inv;
    }
#pragma unroll
    for (int i = 0; i < 8; ++i) {
        int o = bm + ty * 8 + i;
#pragma unroll
        for (int j = 0; j < 8; ++j) {
            int n  = bn + tx * 8 + j;
            int b  = n >> 12;
            int hw = n & 4095;
            float v = fmaf(acc[i][j], scale[i], shift[i]);
            out[((size_t)(b * Oo + o) << 12) + hw] = fmaxf(v, 0.f);
        }
    }
}

// ---------------------------------------------------------------------------
extern "C" void kernel_launch(void* const* d_in, const int* in_sizes, int n_in,
                              void* d_out, int out_size) {
    const float* x      = (const float*)d_in[0];
    const float* w_off  = (const float*)d_in[1];
    const float* b_off  = (const float*)d_in[2];
    const float* weight = (const float*)d_in[3];
    const float* bias   = (const float*)d_in[4];
    const float* gamma  = (const float*)d_in[5];
    const float* beta   = (const float*)d_in[6];
    const float* rmean  = (const float*)d_in[7];
    const float* rvar   = (const float*)d_in[8];
    float* out = (float*)d_out;

    // A: offset conv (27 ch) + sigmoid on mask channels
    offset_conv_kernel<<<Bb * OCOFF * Hh, 64>>>(x, w_off, b_off);

    // B: deform sampling -> cols matrix
    {
        size_t total = (size_t)KTOT * NTOT;
        int threads = 256;
        int blocks = (int)((total + threads - 1) / threads);
        build_cols_kernel<<<blocks, threads>>>(x);
    }

    // C: GEMM + bias + BN + ReLU
    {
        dim3 grid(NTOT / 128, Oo / 128);
        gemm_epilogue_kernel<<<grid, 256>>>(weight, bias, gamma, beta,
                                            rmean, rvar, out);
    }
}

// round 3
// speedup vs baseline: 2.4622x; 2.4622x over previous
#include <cuda_runtime.h>
#include <cuda_bf16.h>
#include <math.h>
#include <stdint.h>

#define Bb   8
#define Cc   256
#define Hh   64
#define Ww   64
#define Oo   256
#define HW   4096
#define OCOFF 27
#define KTOT 2304            /* words per row = original K (C*9); K' = 4608 bf16 */
#define NTOT 32768           /* B*H*W */
#define CSPLIT 8
#define CPG (Cc / CSPLIT)    /* 32 channels per group */

// ---------------- scratch (__device__ globals, allocation-free rule) -------
__device__ float    g_part[CSPLIT][Bb * OCOFF * HW];   // partial offset-conv sums
__device__ float    g_om[Bb * OCOFF * HW];             // off_y | off_x | sigmoid(mask)
__device__ uint32_t g_colsI[(size_t)NTOT * KTOT];      // [n][k] packed (ch,cl) bf16x2
__device__ uint32_t g_A1[Oo * KTOT];                   // (wh, wl) interleaved
__device__ uint32_t g_A2[Oo * KTOT];                   // (wl, wh) interleaved

// ---------------- helpers ---------------------------------------------------
__device__ __forceinline__ uint32_t smem_u32(const void* p) {
    uint32_t a;
    asm("{ .reg .u64 t; cvta.to.shared.u64 t, %1; cvt.u32.u64 %0, t; }" : "=r"(a) : "l"(p));
    return a;
}
__device__ __forceinline__ uint32_t swz(uint32_t off) { return off ^ ((off >> 3) & 0x70); }

__device__ __forceinline__ void cp16(uint32_t dst, const void* src) {
    asm volatile("cp.async.cg.shared.global [%0], [%1], 16;" :: "r"(dst), "l"(src));
}
#define CP_COMMIT() asm volatile("cp.async.commit_group;" ::: "memory")
#define CP_WAIT2()  asm volatile("cp.async.wait_group 2;" ::: "memory")

__device__ __forceinline__ void ldsm4(uint32_t* r, uint32_t addr) {
    asm volatile("ldmatrix.sync.aligned.m8n8.x4.shared.b16 {%0,%1,%2,%3}, [%4];"
                 : "=r"(r[0]), "=r"(r[1]), "=r"(r[2]), "=r"(r[3]) : "r"(addr));
}
__device__ __forceinline__ void mma16816(float* c, const uint32_t* a,
                                         uint32_t b0, uint32_t b1) {
    asm volatile("mma.sync.aligned.m16n8k16.row.col.f32.bf16.bf16.f32 "
                 "{%0,%1,%2,%3}, {%4,%5,%6,%7}, {%8,%9}, {%0,%1,%2,%3};"
                 : "+f"(c[0]), "+f"(c[1]), "+f"(c[2]), "+f"(c[3])
                 : "r"(a[0]), "r"(a[1]), "r"(a[2]), "r"(a[3]), "r"(b0), "r"(b1));
}

// ===========================================================================
// Kernel A1: offset conv partial sums over 32-channel groups
// block = 128 threads (2 rows x 64 w), grid = 8(b) * 32(hslab) * 8(cgroup)
// ===========================================================================
__global__ __launch_bounds__(128)
void offset_conv_part(const float* __restrict__ x,
                      const float* __restrict__ w_off) {
    __shared__ float sx[4][64];
    __shared__ float sw4[27 * 12];

    int cg = blockIdx.x & 7;
    int hs = (blockIdx.x >> 3) & 31;
    int b  = blockIdx.x >> 8;
    int h0 = hs << 1;
    int ty = threadIdx.x >> 6;
    int w  = threadIdx.x & 63;
    int h  = h0 + ty;

    float acc[27];
#pragma unroll
    for (int j = 0; j < 27; ++j) acc[j] = 0.f;

    const float* xb = x + (size_t)b * Cc * HW;
    int c0 = cg * CPG;

    for (int ci = 0; ci < CPG; ++ci) {
        int c = c0 + ci;
#pragma unroll
        for (int r = ty; r < 4; r += 2) {
            int yy = h0 - 1 + r;
            sx[r][w] = (yy >= 0 && yy < Hh) ? xb[(size_t)c * HW + yy * 64 + w] : 0.f;
        }
        for (int i = threadIdx.x; i < 243; i += 128) {
            int oc = i / 9, t = i - oc * 9;
            sw4[oc * 12 + t] = w_off[(size_t)oc * KTOT + c * 9 + t];
        }
        __syncthreads();

        float xv[9];
#pragma unroll
        for (int dy = 0; dy < 3; ++dy)
#pragma unroll
            for (int dx = 0; dx < 3; ++dx) {
                int xx = w - 1 + dx;
                xv[dy * 3 + dx] = (xx >= 0 && xx < Ww) ? sx[ty + dy][xx] : 0.f;
            }

        const float4* swv = (const float4*)sw4;
#pragma unroll
        for (int oc = 0; oc < 27; ++oc) {
            float4 a0 = swv[oc * 3 + 0];
            float4 a1 = swv[oc * 3 + 1];
            float4 a2 = swv[oc * 3 + 2];
            float s = acc[oc];
            s = fmaf(xv[0], a0.x, s); s = fmaf(xv[1], a0.y, s); s = fmaf(xv[2], a0.z, s);
            s = fmaf(xv[3], a0.w, s); s = fmaf(xv[4], a1.x, s); s = fmaf(xv[5], a1.y, s);
            s = fmaf(xv[6], a1.z, s); s = fmaf(xv[7], a1.w, s); s = fmaf(xv[8], a2.x, s);
            acc[oc] = s;
        }
        __syncthreads();
    }

#pragma unroll
    for (int oc = 0; oc < 27; ++oc)
        g_part[cg][((size_t)(b * OCOFF + oc)) * HW + h * 64 + w] = acc[oc];
}

// ===========================================================================
// Kernel A2: reduce partials + bias + sigmoid(mask channels)
// ===========================================================================
__global__ void offset_reduce(const float* __restrict__ b_off) {
    int i = blockIdx.x * 256 + threadIdx.x;
    if (i >= Bb * OCOFF * HW) return;
    float s = 0.f;
#pragma unroll
    for (int g = 0; g < CSPLIT; ++g) s += g_part[g][i];
    int oc = (i >> 12) % OCOFF;
    s += b_off[oc];
    if (oc >= 18) s = 1.f / (1.f + expf(-s));
    g_om[i] = s;
}

// ===========================================================================
// Kernel W: split weights into bf16 hi/lo interleaved pairs
// ===========================================================================
__global__ void wprep_kernel(const float* __restrict__ weight) {
    int idx = blockIdx.x * 256 + threadIdx.x;
    if (idx >= Oo * KTOT) return;
    float wv = weight[idx];
    __nv_bfloat16 wh = __float2bfloat16_rn(wv);
    float whf = __bfloat162float(wh);
    __nv_bfloat16 wl = __float2bfloat16_rn(wv - whf);
    uint32_t hb = __bfloat16_as_ushort(wh);
    uint32_t lb = __bfloat16_as_ushort(wl);
    g_A1[idx] = hb | (lb << 16);
    g_A2[idx] = lb | (hb << 16);
}

// ===========================================================================
// Kernel B: deform-sample -> cols[n][k] packed (ch,cl) bf16x2
// grid = (NTOT/32, KTOT/64), block 256, smem transpose for coalesced stores
// ===========================================================================
__global__ __launch_bounds__(256)
void build_cols_kernel(const float* __restrict__ x) {
    __shared__ uint32_t smt[32][65];

    int n0  = blockIdx.x * 32;
    int kw0 = blockIdx.y * 64;
    int tid = threadIdx.x;
    int n_l = tid & 31;

    int n  = n0 + n_l;
    int b  = n >> 12;
    int hw = n & 4095;
    int h  = hw >> 6;
    int w  = hw & 63;

    const float* omb = g_om + (size_t)b * OCOFF * HW;
    const float* xb  = x + (size_t)b * Cc * HW;

#pragma unroll 1
    for (int pass = 0; pass < 8; ++pass) {
        int kw_l = pass * 8 + (tid >> 5);
        int k = kw0 + kw_l;
        int c = k / 9;
        int kk = k - c * 9;

        float oy = omb[(size_t)kk * HW + hw];
        float ox = omb[(size_t)(9 + kk) * HW + hw];
        float m  = omb[(size_t)(18 + kk) * HW + hw];

        float py = (float)(h - 1 + kk / 3) + oy;
        float px = (float)(w - 1 + kk % 3) + ox;

        float y0f = floorf(py), x0f = floorf(px);
        float wy1 = py - y0f,   wx1 = px - x0f;
        int y0 = (int)y0f, x0 = (int)x0f;

        const float* xc = xb + (size_t)c * HW;
        float v00 = 0.f, v01 = 0.f, v10 = 0.f, v11 = 0.f;
        bool yv0 = (y0 >= 0) & (y0 < Hh);
        bool yv1 = (y0 + 1 >= 0) & (y0 + 1 < Hh);
        bool xv0 = (x0 >= 0) & (x0 < Ww);
        bool xv1 = (x0 + 1 >= 0) & (x0 + 1 < Ww);
        if (yv0 & xv0) v00 = xc[y0 * 64 + x0];
        if (yv0 & xv1) v01 = xc[y0 * 64 + x0 + 1];
        if (yv1 & xv0) v10 = xc[(y0 + 1) * 64 + x0];
        if (yv1 & xv1) v11 = xc[(y0 + 1) * 64 + x0 + 1];

        float val = v00 * (1.f - wy1) * (1.f - wx1)
                  + v01 * (1.f - wy1) * wx1
                  + v10 * wy1 * (1.f - wx1)
                  + v11 * wy1 * wx1;
        val *= m;

        __nv_bfloat16 ch = __float2bfloat16_rn(val);
        float chf = __bfloat162float(ch);
        __nv_bfloat16 cl = __float2bfloat16_rn(val - chf);
        smt[n_l][kw_l] = (uint32_t)__bfloat16_as_ushort(ch)
                       | ((uint32_t)__bfloat16_as_ushort(cl) << 16);
    }
    __syncthreads();

    for (int idx = tid; idx < 32 * 64; idx += 256) {
        int r = idx >> 6, cc = idx & 63;
        g_colsI[(size_t)(n0 + r) * KTOT + kw0 + cc] = smt[r][cc];
    }
}

// ===========================================================================
// Kernel C: HMMA bf16-split GEMM  (M=128, N=128 tiles, K'=4608, 2 A-chains)
// 8 warps (4M x 2N), warp tile 32x64, m16n8k16, cp.async 3-stage pipeline
// ===========================================================================
#define TILEB  16384            /* one 128x(32 word) tile, swizzled */
#define STAGEB (3 * TILEB)      /* A1 | A2 | B */
#define GSM    (3 * STAGEB)     /* 147456 bytes */
#define NCHUNK 72               /* 4608 K' / 64 per chunk */

__device__ __forceinline__ void load_chunk(uint32_t sbu, int stage, int chunk,
                                           int bm, int bn, int r8, int q) {
    int kw = chunk * 32;
    uint32_t sbase = sbu + stage * STAGEB;
#pragma unroll
    for (int rr = 0; rr < 4; ++rr) {
        int row = r8 + rr * 32;
        uint32_t o = swz((uint32_t)(row * 128 + q * 16));
        cp16(sbase + o,             &g_A1[(size_t)(bm + row) * KTOT + kw + q * 4]);
        cp16(sbase + TILEB + o,     &g_A2[(size_t)(bm + row) * KTOT + kw + q * 4]);
        cp16(sbase + 2 * TILEB + o, &g_colsI[(size_t)(bn + row) * KTOT + kw + q * 4]);
    }
}

__global__ __launch_bounds__(256, 1)
void gemm_mma_kernel(const float* __restrict__ bias,
                     const float* __restrict__ gamma,
                     const float* __restrict__ beta,
                     const float* __restrict__ rmean,
                     const float* __restrict__ rvar,
                     float* __restrict__ out) {
    extern __shared__ char smc[];
    uint32_t sbu = smem_u32(smc);
    int tid  = threadIdx.x;
    int lane = tid & 31;
    int wid  = tid >> 5;
    int bn = blockIdx.x * 128;
    int bm = blockIdx.y * 128;
    int warp_m = wid & 3;            // 4 warps along M
    int warp_n = wid >> 2;           // 2 warps along N

    int r8 = tid >> 3, q = tid & 7;

    // ldmatrix per-lane address pieces
    int mi   = lane >> 3;
    int mrow = lane & 7;
    int rbit = ((mi & 1) << 3) + mrow;   // row within 16-row tile
    int cbit = (mi >> 1) << 4;           // 0 or 16 bytes (k half)

    float acc[2][8][4];
#pragma unroll
    for (int a = 0; a < 2; ++a)
#pragma unroll
        for (int b2 = 0; b2 < 8; ++b2)
#pragma unroll
            for (int c2 = 0; c2 < 4; ++c2) acc[a][b2][c2] = 0.f;

    load_chunk(sbu, 0, 0, bm, bn, r8, q); CP_COMMIT();
    load_chunk(sbu, 1, 1, bm, bn, r8, q); CP_COMMIT();
    load_chunk(sbu, 2, 2, bm, bn, r8, q); CP_COMMIT();

    int arow0 = warp_m * 32;
    int brow0 = warp_n * 64;

    for (int i = 0; i < NCHUNK; ++i) {
        int st = i % 3;
        CP_WAIT2();
        __syncthreads();

        uint32_t base = sbu + st * STAGEB;
#pragma unroll
        for (int ks = 0; ks < 4; ++ks) {
            int kb = ks * 32;
            uint32_t a1f[2][4], a2f[2][4], bf[4][4];
#pragma unroll
            for (int mt = 0; mt < 2; ++mt) {
                uint32_t off = swz((uint32_t)((arow0 + mt * 16 + rbit) * 128 + kb + cbit));
                ldsm4(a1f[mt], base + off);
                ldsm4(a2f[mt], base + TILEB + off);
            }
#pragma unroll
            for (int ng = 0; ng < 4; ++ng) {
                uint32_t off = swz((uint32_t)((brow0 + ng * 16 + rbit) * 128 + kb + cbit));
                ldsm4(bf[ng], base + 2 * TILEB + off);
            }
#pragma unroll
            for (int mt = 0; mt < 2; ++mt)
#pragma unroll
                for (int ng = 0; ng < 4; ++ng) {
                    mma16816(acc[mt][ng * 2 + 0], a1f[mt], bf[ng][0], bf[ng][2]);
                    mma16816(acc[mt][ng * 2 + 1], a1f[mt], bf[ng][1], bf[ng][3]);
                    mma16816(acc[mt][ng * 2 + 0], a2f[mt], bf[ng][0], bf[ng][2]);
                    mma16816(acc[mt][ng * 2 + 1], a2f[mt], bf[ng][1], bf[ng][3]);
                }
        }
        __syncthreads();
        if (i + 3 < NCHUNK) load_chunk(sbu, st, i + 3, bm, bn, r8, q);
        CP_COMMIT();
    }

    // epilogue: BN + bias + ReLU, direct float2 stores
    int nbase = bn + warp_n * 64;
#pragma unroll
    for (int mt = 0; mt < 2; ++mt) {
        int o0 = bm + warp_m * 32 + mt * 16 + (lane >> 2);
        int o1 = o0 + 8;
        float inv0 = gamma[o0] * rsqrtf(rvar[o0] + 1e-5f);
        float sh0  = beta[o0] - rmean[o0] * inv0 + bias[o0] * inv0;
        float inv1 = gamma[o1] * rsqrtf(rvar[o1] + 1e-5f);
        float sh1  = beta[o1] - rmean[o1] * inv1 + bias[o1] * inv1;
#pragma unroll
        for (int nt = 0; nt < 8; ++nt) {
            int n = nbase + nt * 8 + ((lane & 3) << 1);
            int bimg = n >> 12;
            int hw   = n & 4095;
            float2 v0, v1;
            v0.x = fmaxf(fmaf(acc[mt][nt][0], inv0, sh0), 0.f);
            v0.y = fmaxf(fmaf(acc[mt][nt][1], inv0, sh0), 0.f);
            v1.x = fmaxf(fmaf(acc[mt][nt][2], inv1, sh1), 0.f);
            v1.y = fmaxf(fmaf(acc[mt][nt][3], inv1, sh1), 0.f);
            *(float2*)&out[(((size_t)(bimg * Oo + o0)) << 12) + hw] = v0;
            *(float2*)&out[(((size_t)(bimg * Oo + o1)) << 12) + hw] = v1;
        }
    }
}

// ===========================================================================
extern "C" void kernel_launch(void* const* d_in, const int* in_sizes, int n_in,
                              void* d_out, int out_size) {
    const float* x      = (const float*)d_in[0];
    const float* w_off  = (const float*)d_in[1];
    const float* b_off  = (const float*)d_in[2];
    const float* weight = (const float*)d_in[3];
    const float* bias   = (const float*)d_in[4];
    const float* gamma  = (const float*)d_in[5];
    const float* beta   = (const float*)d_in[6];
    const float* rmean  = (const float*)d_in[7];
    const float* rvar   = (const float*)d_in[8];
    float* out = (float*)d_out;

    cudaFuncSetAttribute(gemm_mma_kernel,
                         cudaFuncAttributeMaxDynamicSharedMemorySize, GSM);

    wprep_kernel<<<(Oo * KTOT + 255) / 256, 256>>>(weight);

    offset_conv_part<<<Bb * 32 * CSPLIT, 128>>>(x, w_off);
    offset_reduce<<<(Bb * OCOFF * HW + 255) / 256, 256>>>(b_off);

    {
        dim3 grid(NTOT / 32, KTOT / 64);
        build_cols_kernel<<<grid, 256>>>(x);
    }

    {
        dim3 grid(NTOT / 128, Oo / 128);
        gemm_mma_kernel<<<grid, 256, GSM>>>(bias, gamma, beta, rmean, rvar, out);
    }
}

// round 4
// speedup vs baseline: 2.8618x; 1.1623x over previous
#include <cuda_runtime.h>
#include <cuda_bf16.h>
#include <math.h>
#include <stdint.h>

#define Bb   8
#define Cc   256
#define Hh   64
#define Ww   64
#define Oo   256
#define HW   4096
#define OCOFF 27
#define KTOT 2304            /* words per row = original K (C*9) */
#define NTOT 32768           /* B*H*W */
#define CSPLIT 8
#define CPG (Cc / CSPLIT)

// ---------------- scratch (__device__ globals) ------------------------------
__device__ float    g_part[CSPLIT][Bb * OCOFF * HW];
__device__ float    g_om[Bb * OCOFF * HW];
__device__ uint32_t g_colsI[(size_t)NTOT * KTOT];      // [n][k] packed (ch,cl)
__device__ uint32_t g_A1[Oo * KTOT];                   // (wh, wl)
__device__ uint32_t g_A2[Oo * KTOT];                   // (wl, wh)

// ---------------- helpers ----------------------------------------------------
__device__ __forceinline__ uint32_t smem_u32(const void* p) {
    uint32_t a;
    asm("{ .reg .u64 t; cvta.to.shared.u64 t, %1; cvt.u32.u64 %0, t; }" : "=r"(a) : "l"(p));
    return a;
}
__device__ __forceinline__ uint32_t swz(uint32_t off) { return off ^ ((off >> 3) & 0x70); }

__device__ __forceinline__ void cp16(uint32_t dst, const void* src) {
    asm volatile("cp.async.cg.shared.global [%0], [%1], 16;" :: "r"(dst), "l"(src));
}
#define CP_COMMIT() asm volatile("cp.async.commit_group;" ::: "memory")
#define CP_WAIT1()  asm volatile("cp.async.wait_group 1;" ::: "memory")

__device__ __forceinline__ void ldsm4(uint32_t* r, uint32_t addr) {
    asm volatile("ldmatrix.sync.aligned.m8n8.x4.shared.b16 {%0,%1,%2,%3}, [%4];"
                 : "=r"(r[0]), "=r"(r[1]), "=r"(r[2]), "=r"(r[3]) : "r"(addr));
}
__device__ __forceinline__ void mma16816(float* c, const uint32_t* a,
                                         uint32_t b0, uint32_t b1) {
    asm volatile("mma.sync.aligned.m16n8k16.row.col.f32.bf16.bf16.f32 "
                 "{%0,%1,%2,%3}, {%4,%5,%6,%7}, {%8,%9}, {%0,%1,%2,%3};"
                 : "+f"(c[0]), "+f"(c[1]), "+f"(c[2]), "+f"(c[3])
                 : "r"(a[0]), "r"(a[1]), "r"(a[2]), "r"(a[3]), "r"(b0), "r"(b1));
}
__device__ __forceinline__ void fma2(unsigned long long& a, unsigned long long x,
                                     unsigned long long w) {
    asm("fma.rn.f32x2 %0, %1, %2, %0;" : "+l"(a) : "l"(x), "l"(w));
}
__device__ __forceinline__ unsigned long long pack2(float v) {
    unsigned long long r;
    asm("mov.b64 %0, {%1, %1};" : "=l"(r) : "r"(__float_as_uint(v)));
    return r;
}

// ===========================================================================
// Kernel A1: offset conv partials (32-ch groups), packed f32x2 math
// block 128 (2 rows x 64 w), grid = 8(b)*32(hslab)*8(cgroup)
// ===========================================================================
__global__ __launch_bounds__(128)
void offset_conv_part(const float* __restrict__ x,
                      const float* __restrict__ w_off) {
    __shared__ float sx[4][64];
    __shared__ __align__(16) float sw2[9 * 28];   // [t][oc], oc padded to 28

    int cg = blockIdx.x & 7;
    int hs = (blockIdx.x >> 3) & 31;
    int b  = blockIdx.x >> 8;
    int h0 = hs << 1;
    int ty = threadIdx.x >> 6;
    int w  = threadIdx.x & 63;
    int h  = h0 + ty;

    if (threadIdx.x < 9) sw2[threadIdx.x * 28 + 27] = 0.f;   // pad oc=27

    unsigned long long acc2[14];
#pragma unroll
    for (int j = 0; j < 14; ++j) acc2[j] = 0ULL;

    const float* xb = x + (size_t)b * Cc * HW;
    int c0 = cg * CPG;

    for (int ci = 0; ci < CPG; ++ci) {
        int c = c0 + ci;
#pragma unroll
        for (int r = ty; r < 4; r += 2) {
            int yy = h0 - 1 + r;
            sx[r][w] = (yy >= 0 && yy < Hh) ? xb[(size_t)c * HW + yy * 64 + w] : 0.f;
        }
        for (int i = threadIdx.x; i < 243; i += 128) {
            int oc = i / 9, t = i - oc * 9;
            sw2[t * 28 + oc] = w_off[(size_t)oc * KTOT + c * 9 + t];
        }
        __syncthreads();

        float xv[9];
#pragma unroll
        for (int dy = 0; dy < 3; ++dy)
#pragma unroll
            for (int dx = 0; dx < 3; ++dx) {
                int xx = w - 1 + dx;
                xv[dy * 3 + dx] = (xx >= 0 && xx < Ww) ? sx[ty + dy][xx] : 0.f;
            }

#pragma unroll
        for (int t = 0; t < 9; ++t) {
            unsigned long long xp = pack2(xv[t]);
            const ulonglong2* wp = (const ulonglong2*)&sw2[t * 28];
#pragma unroll
            for (int j = 0; j < 7; ++j) {
                ulonglong2 w2 = wp[j];
                fma2(acc2[2 * j],     xp, w2.x);
                fma2(acc2[2 * j + 1], xp, w2.y);
            }
        }
        __syncthreads();
    }

    size_t outb = ((size_t)b * OCOFF) * HW + h * 64 + w;
#pragma unroll
    for (int j = 0; j < 14; ++j) {
        float lo = __uint_as_float((uint32_t)acc2[j]);
        float hi = __uint_as_float((uint32_t)(acc2[j] >> 32));
        int oc0 = 2 * j, oc1 = 2 * j + 1;
        g_part[cg][outb + (size_t)oc0 * HW] = lo;
        if (oc1 < OCOFF) g_part[cg][outb + (size_t)oc1 * HW] = hi;
    }
}

// ===========================================================================
// Kernel A2: reduce partials + bias + sigmoid(mask channels)
// ===========================================================================
__global__ void offset_reduce(const float* __restrict__ b_off) {
    int i = blockIdx.x * 256 + threadIdx.x;
    if (i >= Bb * OCOFF * HW) return;
    float s = 0.f;
#pragma unroll
    for (int g = 0; g < CSPLIT; ++g) s += g_part[g][i];
    int oc = (i >> 12) % OCOFF;
    s += b_off[oc];
    if (oc >= 18) s = 1.f / (1.f + expf(-s));
    g_om[i] = s;
}

// ===========================================================================
// Kernel W: split weights into bf16 hi/lo interleaved pairs
// ===========================================================================
__global__ void wprep_kernel(const float* __restrict__ weight) {
    int idx = blockIdx.x * 256 + threadIdx.x;
    if (idx >= Oo * KTOT) return;
    float wv = weight[idx];
    __nv_bfloat16 wh = __float2bfloat16_rn(wv);
    float whf = __bfloat162float(wh);
    __nv_bfloat16 wl = __float2bfloat16_rn(wv - whf);
    uint32_t hb = __bfloat16_as_ushort(wh);
    uint32_t lb = __bfloat16_as_ushort(wl);
    g_A1[idx] = hb | (lb << 16);
    g_A2[idx] = lb | (hb << 16);
}

// ===========================================================================
// Kernel B: deform-sample -> cols[n][k] packed (ch,cl) bf16x2
// Phase 1: precompute 288 (n_l, kk) sampling param sets (weights premult by
// mask, clamped offsets). Phase 2: 4 gathers + 4 fma per element.
// ===========================================================================
__global__ __launch_bounds__(256)
void build_cols_kernel(const float* __restrict__ x) {
    __shared__ float4 sw[288];     // mask-premult bilinear weights
    __shared__ int4   so[288];     // clamped gather offsets
    __shared__ uint32_t smt[32][65];

    int n0  = blockIdx.x * 32;
    int kw0 = blockIdx.y * 64;
    int tid = threadIdx.x;

    // phase 1
    for (int i = tid; i < 288; i += 256) {
        int n_l = i & 31;
        int kk  = i >> 5;          // 0..8
        int n = n0 + n_l;
        int b = n >> 12;
        int hw = n & 4095;
        int h = hw >> 6, w = hw & 63;
        const float* omb = g_om + (size_t)b * OCOFF * HW;
        float oy = omb[(size_t)kk * HW + hw];
        float ox = omb[(size_t)(9 + kk) * HW + hw];
        float m  = omb[(size_t)(18 + kk) * HW + hw];

        float py = (float)(h - 1 + kk / 3) + oy;
        float px = (float)(w - 1 + kk % 3) + ox;
        float y0f = floorf(py), x0f = floorf(px);
        float wy = py - y0f, wx = px - x0f;
        int y0 = (int)y0f, x0 = (int)x0f;

        bool yv0 = (y0 >= 0) & (y0 < Hh);
        bool yv1 = (y0 + 1 >= 0) & (y0 + 1 < Hh);
        bool xv0 = (x0 >= 0) & (x0 < Ww);
        bool xv1 = (x0 + 1 >= 0) & (x0 + 1 < Ww);

        float4 wv;
        wv.x = m * (1.f - wy) * (1.f - wx) * (float)(yv0 & xv0);
        wv.y = m * (1.f - wy) * wx         * (float)(yv0 & xv1);
        wv.z = m * wy * (1.f - wx)         * (float)(yv1 & xv0);
        wv.w = m * wy * wx                 * (float)(yv1 & xv1);

        int y0c = min(max(y0, 0), Hh - 1);
        int y1c = min(max(y0 + 1, 0), Hh - 1);
        int x0c = min(max(x0, 0), Ww - 1);
        int x1c = min(max(x0 + 1, 0), Ww - 1);
        int4 ov;
        ov.x = y0c * 64 + x0c;
        ov.y = y0c * 64 + x1c;
        ov.z = y1c * 64 + x0c;
        ov.w = y1c * 64 + x1c;

        sw[kk * 32 + n_l] = wv;
        so[kk * 32 + n_l] = ov;
    }
    __syncthreads();

    // phase 2
    int n_l = tid & 31;
    int kg  = tid >> 5;            // 0..7
    int n = n0 + n_l;
    int b = n >> 12;
    const float* xbase = x + (size_t)b * Cc * HW;

    int k0 = kw0 + kg;
    int c  = k0 / 9;
    int kk = k0 - c * 9;

#pragma unroll
    for (int pass = 0; pass < 8; ++pass) {
        float4 wv = sw[kk * 32 + n_l];
        int4   ov = so[kk * 32 + n_l];
        const float* xc = xbase + (size_t)c * HW;
        float val = xc[ov.x] * wv.x + xc[ov.y] * wv.y
                  + xc[ov.z] * wv.z + xc[ov.w] * wv.w;

        __nv_bfloat16 ch = __float2bfloat16_rn(val);
        float chf = __bfloat162float(ch);
        __nv_bfloat16 cl = __float2bfloat16_rn(val - chf);
        smt[n_l][pass * 8 + kg] = (uint32_t)__bfloat16_as_ushort(ch)
                                | ((uint32_t)__bfloat16_as_ushort(cl) << 16);
        // advance k by 8
        kk += 8;
        if (kk >= 9) { kk -= 9; ++c; }
    }
    __syncthreads();

    for (int idx = tid; idx < 32 * 64; idx += 256) {
        int r = idx >> 6, cc = idx & 63;
        g_colsI[(size_t)(n0 + r) * KTOT + kw0 + cc] = smt[r][cc];
    }
}

// ===========================================================================
// Kernel C: HMMA bf16-split GEMM, M=256 (whole O) x N=128 tiles, K'=4608
// 512 threads, 16 warps (8M x 2N), 2-stage cp.async, chain-major inner loop
// ===========================================================================
#define A_TILE 32768            /* 256 rows x 128B */
#define B_TILE 16384            /* 128 rows x 128B */
#define STAGEB (2 * A_TILE + B_TILE)   /* 81920 */
#define GSM    (2 * STAGEB)            /* 163840 */
#define NCHUNK 72

__device__ __forceinline__ void load_chunk(uint32_t sbu, int st, int chunk,
                                           int bn, int r, int q) {
    int kw = chunk * 32;
    uint32_t base = sbu + st * STAGEB;
#pragma unroll
    for (int rr = 0; rr < 4; ++rr) {
        int row = r + rr * 64;            // 0..255
        uint32_t o = swz((uint32_t)(row * 128 + q * 16));
        cp16(base + o,          &g_A1[(size_t)row * KTOT + kw + q * 4]);
        cp16(base + A_TILE + o, &g_A2[(size_t)row * KTOT + kw + q * 4]);
    }
#pragma unroll
    for (int rr = 0; rr < 2; ++rr) {
        int row = r + rr * 64;            // 0..127
        uint32_t o = swz((uint32_t)(row * 128 + q * 16));
        cp16(base + 2 * A_TILE + o, &g_colsI[(size_t)(bn + row) * KTOT + kw + q * 4]);
    }
}

__global__ __launch_bounds__(512, 1)
void gemm_mma_kernel(const float* __restrict__ bias,
                     const float* __restrict__ gamma,
                     const float* __restrict__ beta,
                     const float* __restrict__ rmean,
                     const float* __restrict__ rvar,
                     float* __restrict__ out) {
    extern __shared__ char smc[];
    uint32_t sbu = smem_u32(smc);
    int tid  = threadIdx.x;
    int lane = tid & 31;
    int wid  = tid >> 5;
    int bn = blockIdx.x * 128;
    int warp_m = wid & 7;                 // 8 warps along M (256)
    int warp_n = wid >> 3;                // 2 warps along N (128)

    int r = tid >> 3, q = tid & 7;

    int mi   = lane >> 3;
    int mrow = lane & 7;
    int rbit = ((mi & 1) << 3) + mrow;
    int cbit = (mi >> 1) << 4;

    float acc[2][8][4];
#pragma unroll
    for (int a = 0; a < 2; ++a)
#pragma unroll
        for (int b2 = 0; b2 < 8; ++b2)
#pragma unroll
            for (int c2 = 0; c2 < 4; ++c2) acc[a][b2][c2] = 0.f;

    load_chunk(sbu, 0, 0, bn, r, q); CP_COMMIT();
    load_chunk(sbu, 1, 1, bn, r, q); CP_COMMIT();

    int arow0 = warp_m * 32;
    int brow0 = warp_n * 64;

    for (int i = 0; i < NCHUNK; ++i) {
        int st = i & 1;
        CP_WAIT1();
        __syncthreads();

        uint32_t base = sbu + st * STAGEB;
#pragma unroll
        for (int ks = 0; ks < 4; ++ks) {
            int kb = ks * 32;
            uint32_t bf[4][4];
#pragma unroll
            for (int ng = 0; ng < 4; ++ng) {
                uint32_t off = swz((uint32_t)((brow0 + ng * 16 + rbit) * 128 + kb + cbit));
                ldsm4(bf[ng], base + 2 * A_TILE + off);
            }
            // chain A1 (16 independent accumulator targets)
#pragma unroll
            for (int mt = 0; mt < 2; ++mt) {
                uint32_t af[4];
                uint32_t off = swz((uint32_t)((arow0 + mt * 16 + rbit) * 128 + kb + cbit));
                ldsm4(af, base + off);
#pragma unroll
                for (int ng = 0; ng < 4; ++ng) {
                    mma16816(acc[mt][ng * 2 + 0], af, bf[ng][0], bf[ng][2]);
                    mma16816(acc[mt][ng * 2 + 1], af, bf[ng][1], bf[ng][3]);
                }
            }
            // chain A2
#pragma unroll
            for (int mt = 0; mt < 2; ++mt) {
                uint32_t af[4];
                uint32_t off = swz((uint32_t)((arow0 + mt * 16 + rbit) * 128 + kb + cbit));
                ldsm4(af, base + A_TILE + off);
#pragma unroll
                for (int ng = 0; ng < 4; ++ng) {
                    mma16816(acc[mt][ng * 2 + 0], af, bf[ng][0], bf[ng][2]);
                    mma16816(acc[mt][ng * 2 + 1], af, bf[ng][1], bf[ng][3]);
                }
            }
        }
        __syncthreads();
        if (i + 2 < NCHUNK) load_chunk(sbu, st, i + 2, bn, r, q);
        CP_COMMIT();
    }

    // epilogue: BN + bias + ReLU, float2 stores
    int nbase = bn + warp_n * 64;
#pragma unroll
    for (int mt = 0; mt < 2; ++mt) {
        int o0 = warp_m * 32 + mt * 16 + (lane >> 2);
        int o1 = o0 + 8;
        float inv0 = gamma[o0] * rsqrtf(rvar[o0] + 1e-5f);
        float sh0  = beta[o0] - rmean[o0] * inv0 + bias[o0] * inv0;
        float inv1 = gamma[o1] * rsqrtf(rvar[o1] + 1e-5f);
        float sh1  = beta[o1] - rmean[o1] * inv1 + bias[o1] * inv1;
#pragma unroll
        for (int nt = 0; nt < 8; ++nt) {
            int n = nbase + nt * 8 + ((lane & 3) << 1);
            int bimg = n >> 12;
            int hw   = n & 4095;
            float2 v0, v1;
            v0.x = fmaxf(fmaf(acc[mt][nt][0], inv0, sh0), 0.f);
            v0.y = fmaxf(fmaf(acc[mt][nt][1], inv0, sh0), 0.f);
            v1.x = fmaxf(fmaf(acc[mt][nt][2], inv1, sh1), 0.f);
            v1.y = fmaxf(fmaf(acc[mt][nt][3], inv1, sh1), 0.f);
            *(float2*)&out[(((size_t)(bimg * Oo + o0)) << 12) + hw] = v0;
            *(float2*)&out[(((size_t)(bimg * Oo + o1)) << 12) + hw] = v1;
        }
    }
}

// ===========================================================================
extern "C" void kernel_launch(void* const* d_in, const int* in_sizes, int n_in,
                              void* d_out, int out_size) {
    const float* x      = (const float*)d_in[0];
    const float* w_off  = (const float*)d_in[1];
    const float* b_off  = (const float*)d_in[2];
    const float* weight = (const float*)d_in[3];
    const float* bias   = (const float*)d_in[4];
    const float* gamma  = (const float*)d_in[5];
    const float* beta   = (const float*)d_in[6];
    const float* rmean  = (const float*)d_in[7];
    const float* rvar   = (const float*)d_in[8];
    float* out = (float*)d_out;

    cudaFuncSetAttribute(gemm_mma_kernel,
                         cudaFuncAttributeMaxDynamicSharedMemorySize, GSM);

    wprep_kernel<<<(Oo * KTOT + 255) / 256, 256>>>(weight);

    offset_conv_part<<<Bb * 32 * CSPLIT, 128>>>(x, w_off);
    offset_reduce<<<(Bb * OCOFF * HW + 255) / 256, 256>>>(b_off);

    {
        dim3 grid(NTOT / 32, KTOT / 64);
        build_cols_kernel<<<grid, 256>>>(x);
    }

    {
        dim3 grid(NTOT / 128);
        gemm_mma_kernel<<<grid, 512, GSM>>>(bias, gamma, beta, rmean, rvar, out);
    }
}

// round 5
// speedup vs baseline: 3.1710x; 1.1080x over previous
#include <cuda_runtime.h>
#include <cuda_bf16.h>
#include <math.h>
#include <stdint.h>

#define Bb   8
#define Cc   256
#define Hh   64
#define Ww   64
#define Oo   256
#define HW   4096
#define OCOFF 27
#define KTOT 2304            /* bf16 elements per row (C*9) */
#define NTOT 32768           /* B*H*W */
#define CSPLIT 8
#define CPG (Cc / CSPLIT)

// ---------------- scratch (__device__ globals) ------------------------------
__device__ float    g_part[CSPLIT][Bb * OCOFF * HW];
__device__ float    g_om[Bb * OCOFF * HW];
__device__ uint16_t g_colsH[(size_t)NTOT * KTOT];   // bf16 hi plane
__device__ uint16_t g_colsL[(size_t)NTOT * KTOT];   // bf16 lo plane
__device__ uint16_t g_AH[Oo * KTOT];                // weight hi
__device__ uint16_t g_AL[Oo * KTOT];                // weight lo

// ---------------- helpers ----------------------------------------------------
__device__ __forceinline__ uint32_t smem_u32(const void* p) {
    uint32_t a;
    asm("{ .reg .u64 t; cvta.to.shared.u64 t, %1; cvt.u32.u64 %0, t; }" : "=r"(a) : "l"(p));
    return a;
}
__device__ __forceinline__ uint32_t swz(uint32_t off) { return off ^ ((off >> 3) & 0x70); }

__device__ __forceinline__ void cp16(uint32_t dst, const void* src) {
    asm volatile("cp.async.cg.shared.global [%0], [%1], 16;" :: "r"(dst), "l"(src));
}
#define CP_COMMIT() asm volatile("cp.async.commit_group;" ::: "memory")
#define CP_WAIT1()  asm volatile("cp.async.wait_group 1;" ::: "memory")

__device__ __forceinline__ void ldsm4(uint32_t* r, uint32_t addr) {
    asm volatile("ldmatrix.sync.aligned.m8n8.x4.shared.b16 {%0,%1,%2,%3}, [%4];"
                 : "=r"(r[0]), "=r"(r[1]), "=r"(r[2]), "=r"(r[3]) : "r"(addr));
}
__device__ __forceinline__ void mma16816(float* c, const uint32_t* a,
                                         uint32_t b0, uint32_t b1) {
    asm volatile("mma.sync.aligned.m16n8k16.row.col.f32.bf16.bf16.f32 "
                 "{%0,%1,%2,%3}, {%4,%5,%6,%7}, {%8,%9}, {%0,%1,%2,%3};"
                 : "+f"(c[0]), "+f"(c[1]), "+f"(c[2]), "+f"(c[3])
                 : "r"(a[0]), "r"(a[1]), "r"(a[2]), "r"(a[3]), "r"(b0), "r"(b1));
}
__device__ __forceinline__ void fma2(unsigned long long& a, unsigned long long x,
                                     unsigned long long w) {
    asm("fma.rn.f32x2 %0, %1, %2, %0;" : "+l"(a) : "l"(x), "l"(w));
}
__device__ __forceinline__ unsigned long long pack2(float v) {
    unsigned long long r;
    asm("mov.b64 %0, {%1, %1};" : "=l"(r) : "r"(__float_as_uint(v)));
    return r;
}

// ===========================================================================
// Kernel A1: offset conv partials (32-ch groups), packed f32x2 math
// ===========================================================================
__global__ __launch_bounds__(128)
void offset_conv_part(const float* __restrict__ x,
                      const float* __restrict__ w_off) {
    __shared__ float sx[4][64];
    __shared__ __align__(16) float sw2[9 * 28];

    int cg = blockIdx.x & 7;
    int hs = (blockIdx.x >> 3) & 31;
    int b  = blockIdx.x >> 8;
    int h0 = hs << 1;
    int ty = threadIdx.x >> 6;
    int w  = threadIdx.x & 63;
    int h  = h0 + ty;

    if (threadIdx.x < 9) sw2[threadIdx.x * 28 + 27] = 0.f;

    unsigned long long acc2[14];
#pragma unroll
    for (int j = 0; j < 14; ++j) acc2[j] = 0ULL;

    const float* xb = x + (size_t)b * Cc * HW;
    int c0 = cg * CPG;

    for (int ci = 0; ci < CPG; ++ci) {
        int c = c0 + ci;
#pragma unroll
        for (int r = ty; r < 4; r += 2) {
            int yy = h0 - 1 + r;
            sx[r][w] = (yy >= 0 && yy < Hh) ? xb[(size_t)c * HW + yy * 64 + w] : 0.f;
        }
        for (int i = threadIdx.x; i < 243; i += 128) {
            int oc = i / 9, t = i - oc * 9;
            sw2[t * 28 + oc] = w_off[(size_t)oc * KTOT + c * 9 + t];
        }
        __syncthreads();

        float xv[9];
#pragma unroll
        for (int dy = 0; dy < 3; ++dy)
#pragma unroll
            for (int dx = 0; dx < 3; ++dx) {
                int xx = w - 1 + dx;
                xv[dy * 3 + dx] = (xx >= 0 && xx < Ww) ? sx[ty + dy][xx] : 0.f;
            }

#pragma unroll
        for (int t = 0; t < 9; ++t) {
            unsigned long long xp = pack2(xv[t]);
            const ulonglong2* wp = (const ulonglong2*)&sw2[t * 28];
#pragma unroll
            for (int j = 0; j < 7; ++j) {
                ulonglong2 w2 = wp[j];
                fma2(acc2[2 * j],     xp, w2.x);
                fma2(acc2[2 * j + 1], xp, w2.y);
            }
        }
        __syncthreads();
    }

    size_t outb = ((size_t)b * OCOFF) * HW + h * 64 + w;
#pragma unroll
    for (int j = 0; j < 14; ++j) {
        float lo = __uint_as_float((uint32_t)acc2[j]);
        float hi = __uint_as_float((uint32_t)(acc2[j] >> 32));
        int oc0 = 2 * j, oc1 = 2 * j + 1;
        g_part[cg][outb + (size_t)oc0 * HW] = lo;
        if (oc1 < OCOFF) g_part[cg][outb + (size_t)oc1 * HW] = hi;
    }
}

// ===========================================================================
// Kernel A2: reduce partials + bias + sigmoid(mask channels)
// ===========================================================================
__global__ void offset_reduce(const float* __restrict__ b_off) {
    int i = blockIdx.x * 256 + threadIdx.x;
    if (i >= Bb * OCOFF * HW) return;
    float s = 0.f;
#pragma unroll
    for (int g = 0; g < CSPLIT; ++g) s += g_part[g][i];
    int oc = (i >> 12) % OCOFF;
    s += b_off[oc];
    if (oc >= 18) s = 1.f / (1.f + expf(-s));
    g_om[i] = s;
}

// ===========================================================================
// Kernel W: split weights into bf16 hi (truncate) / lo (residual) planes
// ===========================================================================
__global__ void wprep_kernel(const float* __restrict__ weight) {
    int idx = blockIdx.x * 256 + threadIdx.x;
    if (idx >= Oo * KTOT) return;
    float wv = weight[idx];
    uint32_t vb = __float_as_uint(wv);
    uint32_t hb = vb & 0xFFFF0000u;
    float resid = wv - __uint_as_float(hb);
    g_AH[idx] = (uint16_t)(hb >> 16);
    g_AL[idx] = __bfloat16_as_ushort(__float2bfloat16_rn(resid));
}

// ===========================================================================
// Kernel B: deform-sample -> planar bf16 hi/lo cols.
// 288 threads = 32 n x 9 kk. Params in registers; loop 256 channels.
// ===========================================================================
__global__ __launch_bounds__(288)
void build_cols_kernel(const float* __restrict__ x) {
    __shared__ uint32_t smt[32][73];   // padded: conflict-free STS

    int tid = threadIdx.x;
    int n_l = tid & 31;
    int kk  = tid >> 5;                // 0..8
    int n0  = blockIdx.x * 32;
    int n   = n0 + n_l;
    int b   = n >> 12;
    int hw  = n & 4095;
    int h   = hw >> 6, w = hw & 63;

    // per-(n,kk) sampling params, in registers
    const float* omb = g_om + (size_t)b * OCOFF * HW;
    float oy = omb[(size_t)kk * HW + hw];
    float ox = omb[(size_t)(9 + kk) * HW + hw];
    float m  = omb[(size_t)(18 + kk) * HW + hw];

    float py = (float)(h - 1 + kk / 3) + oy;
    float px = (float)(w - 1 + kk % 3) + ox;
    float y0f = floorf(py), x0f = floorf(px);
    float wy = py - y0f, wx = px - x0f;
    int y0 = (int)y0f, x0 = (int)x0f;

    bool yv0 = (y0 >= 0) & (y0 < Hh);
    bool yv1 = (y0 + 1 >= 0) & (y0 + 1 < Hh);
    bool xv0 = (x0 >= 0) & (x0 < Ww);
    bool xv1 = (x0 + 1 >= 0) & (x0 + 1 < Ww);

    float w00 = m * (1.f - wy) * (1.f - wx) * (float)(yv0 & xv0);
    float w01 = m * (1.f - wy) * wx         * (float)(yv0 & xv1);
    float w10 = m * wy * (1.f - wx)         * (float)(yv1 & xv0);
    float w11 = m * wy * wx                 * (float)(yv1 & xv1);

    int y0c = min(max(y0, 0), Hh - 1);
    int y1c = min(max(y0 + 1, 0), Hh - 1);
    int x0c = min(max(x0, 0), Ww - 1);
    int x1c = min(max(x0 + 1, 0), Ww - 1);
    int o00 = y0c * 64 + x0c, o01 = y0c * 64 + x1c;
    int o10 = y1c * 64 + x0c, o11 = y1c * 64 + x1c;

    const float* xb = x + (size_t)b * Cc * HW;
    int rr = tid / 9, jj = tid - rr * 9;   // output-stage coords

#pragma unroll 1
    for (int chunk = 0; chunk < 32; ++chunk) {
        int c0 = chunk * 8;
#pragma unroll
        for (int cl = 0; cl < 8; ++cl) {
            const float* xc = xb + (size_t)(c0 + cl) * HW;
            float val = xc[o00] * w00 + xc[o01] * w01
                      + xc[o10] * w10 + xc[o11] * w11;
            uint32_t vb = __float_as_uint(val);
            uint32_t hb = vb & 0xFFFF0000u;
            float resid = val - __uint_as_float(hb);
            uint32_t lb = __bfloat16_as_ushort(__float2bfloat16_rn(resid));
            smt[n_l][cl * 9 + kk] = (hb >> 16) | (lb << 16);
        }
        __syncthreads();

        // write out 32 rows x 72 elements per plane: 288 uint4 each
        uint32_t v[8];
#pragma unroll
        for (int i = 0; i < 8; ++i) v[i] = smt[rr][jj * 8 + i];
        uint4 ph, pl;
        ph.x = (v[0] & 0xFFFFu) | (v[1] << 16);
        ph.y = (v[2] & 0xFFFFu) | (v[3] << 16);
        ph.z = (v[4] & 0xFFFFu) | (v[5] << 16);
        ph.w = (v[6] & 0xFFFFu) | (v[7] << 16);
        pl.x = (v[0] >> 16) | (v[1] & 0xFFFF0000u);
        pl.y = (v[2] >> 16) | (v[3] & 0xFFFF0000u);
        pl.z = (v[4] >> 16) | (v[5] & 0xFFFF0000u);
        pl.w = (v[6] >> 16) | (v[7] & 0xFFFF0000u);
        size_t base = (size_t)(n0 + rr) * KTOT + chunk * 72 + jj * 8;
        *(uint4*)&g_colsH[base] = ph;
        *(uint4*)&g_colsL[base] = pl;
        __syncthreads();
    }
}

// ===========================================================================
// Kernel C: HMMA 3-term bf16 GEMM.  M=256 x N=128 tiles, K=2304 per chain.
// out = AH*BH + AL*BH + AH*BL   (AL*BL dropped, ~2^-16)
// 512 threads, 16 warps (8M x 2N), 2-stage cp.async, K-chunk 64.
// ===========================================================================
#define AT 32768                 /* 256 rows x 128B */
#define BT 16384                 /* 128 rows x 128B */
#define STAGEB (2 * AT + 2 * BT) /* 98304 */
#define GSM    (2 * STAGEB)      /* 196608 */
#define NCHUNK 36

__device__ __forceinline__ void load_chunk(uint32_t sbu, int st, int chunk,
                                           int bn, int r, int q) {
    int kw = chunk * 64;
    uint32_t base = sbu + st * STAGEB;
#pragma unroll
    for (int rr = 0; rr < 4; ++rr) {
        int row = r + rr * 64;
        uint32_t o = swz((uint32_t)(row * 128 + q * 16));
        cp16(base + o,      &g_AH[(size_t)row * KTOT + kw + q * 8]);
        cp16(base + AT + o, &g_AL[(size_t)row * KTOT + kw + q * 8]);
    }
#pragma unroll
    for (int rr = 0; rr < 2; ++rr) {
        int row = r + rr * 64;
        uint32_t o = swz((uint32_t)(row * 128 + q * 16));
        cp16(base + 2 * AT + o,      &g_colsH[(size_t)(bn + row) * KTOT + kw + q * 8]);
        cp16(base + 2 * AT + BT + o, &g_colsL[(size_t)(bn + row) * KTOT + kw + q * 8]);
    }
}

__global__ __launch_bounds__(512, 1)
void gemm_mma_kernel(const float* __restrict__ bias,
                     const float* __restrict__ gamma,
                     const float* __restrict__ beta,
                     const float* __restrict__ rmean,
                     const float* __restrict__ rvar,
                     float* __restrict__ out) {
    extern __shared__ char smc[];
    uint32_t sbu = smem_u32(smc);
    int tid  = threadIdx.x;
    int lane = tid & 31;
    int wid  = tid >> 5;
    int bn = blockIdx.x * 128;
    int warp_m = wid & 7;
    int warp_n = wid >> 3;

    int r = tid >> 3, q = tid & 7;

    int mi   = lane >> 3;
    int mrow = lane & 7;
    int rbit = ((mi & 1) << 3) + mrow;
    int cbit = (mi >> 1) << 4;

    float acc[2][8][4];
#pragma unroll
    for (int a = 0; a < 2; ++a)
#pragma unroll
        for (int b2 = 0; b2 < 8; ++b2)
#pragma unroll
            for (int c2 = 0; c2 < 4; ++c2) acc[a][b2][c2] = 0.f;

    load_chunk(sbu, 0, 0, bn, r, q); CP_COMMIT();
    load_chunk(sbu, 1, 1, bn, r, q); CP_COMMIT();

    int arow0 = warp_m * 32;
    int brow0 = warp_n * 64;

    for (int i = 0; i < NCHUNK; ++i) {
        int st = i & 1;
        CP_WAIT1();
        __syncthreads();

        uint32_t base = sbu + st * STAGEB;
#pragma unroll
        for (int ks = 0; ks < 4; ++ks) {
            int kb = ks * 32;
            uint32_t boffs[4], aoffs[2];
#pragma unroll
            for (int ng = 0; ng < 4; ++ng)
                boffs[ng] = swz((uint32_t)((brow0 + ng * 16 + rbit) * 128 + kb + cbit));
#pragma unroll
            for (int mt = 0; mt < 2; ++mt)
                aoffs[mt] = swz((uint32_t)((arow0 + mt * 16 + rbit) * 128 + kb + cbit));

            uint32_t bq[4][4], ah[2][4];
#pragma unroll
            for (int ng = 0; ng < 4; ++ng) ldsm4(bq[ng], base + 2 * AT + boffs[ng]);
#pragma unroll
            for (int mt = 0; mt < 2; ++mt) ldsm4(ah[mt], base + aoffs[mt]);

            // AH x BH
#pragma unroll
            for (int mt = 0; mt < 2; ++mt)
#pragma unroll
                for (int ng = 0; ng < 4; ++ng) {
                    mma16816(acc[mt][ng * 2 + 0], ah[mt], bq[ng][0], bq[ng][2]);
                    mma16816(acc[mt][ng * 2 + 1], ah[mt], bq[ng][1], bq[ng][3]);
                }
            // AL x BH
#pragma unroll
            for (int mt = 0; mt < 2; ++mt) {
                uint32_t al[4];
                ldsm4(al, base + AT + aoffs[mt]);
#pragma unroll
                for (int ng = 0; ng < 4; ++ng) {
                    mma16816(acc[mt][ng * 2 + 0], al, bq[ng][0], bq[ng][2]);
                    mma16816(acc[mt][ng * 2 + 1], al, bq[ng][1], bq[ng][3]);
                }
            }
            // AH x BL (reuse bq regs)
#pragma unroll
            for (int ng = 0; ng < 4; ++ng) ldsm4(bq[ng], base + 2 * AT + BT + boffs[ng]);
#pragma unroll
            for (int mt = 0; mt < 2; ++mt)
#pragma unroll
                for (int ng = 0; ng < 4; ++ng) {
                    mma16816(acc[mt][ng * 2 + 0], ah[mt], bq[ng][0], bq[ng][2]);
                    mma16816(acc[mt][ng * 2 + 1], ah[mt], bq[ng][1], bq[ng][3]);
                }
        }
        __syncthreads();
        if (i + 2 < NCHUNK) load_chunk(sbu, st, i + 2, bn, r, q);
        CP_COMMIT();
    }

    // epilogue: BN + bias + ReLU, float2 stores
    int nbase = bn + warp_n * 64;
#pragma unroll
    for (int mt = 0; mt < 2; ++mt) {
        int o0 = warp_m * 32 + mt * 16 + (lane >> 2);
        int o1 = o0 + 8;
        float inv0 = gamma[o0] * rsqrtf(rvar[o0] + 1e-5f);
        float sh0  = beta[o0] - rmean[o0] * inv0 + bias[o0] * inv0;
        float inv1 = gamma[o1] * rsqrtf(rvar[o1] + 1e-5f);
        float sh1  = beta[o1] - rmean[o1] * inv1 + bias[o1] * inv1;
#pragma unroll
        for (int nt = 0; nt < 8; ++nt) {
            int n = nbase + nt * 8 + ((lane & 3) << 1);
            int bimg = n >> 12;
            int hw   = n & 4095;
            float2 v0, v1;
            v0.x = fmaxf(fmaf(acc[mt][nt][0], inv0, sh0), 0.f);
            v0.y = fmaxf(fmaf(acc[mt][nt][1], inv0, sh0), 0.f);
            v1.x = fmaxf(fmaf(acc[mt][nt][2], inv1, sh1), 0.f);
            v1.y = fmaxf(fmaf(acc[mt][nt][3], inv1, sh1), 0.f);
            *(float2*)&out[(((size_t)(bimg * Oo + o0)) << 12) + hw] = v0;
            *(float2*)&out[(((size_t)(bimg * Oo + o1)) << 12) + hw] = v1;
        }
    }
}

// ===========================================================================
extern "C" void kernel_launch(void* const* d_in, const int* in_sizes, int n_in,
                              void* d_out, int out_size) {
    const float* x      = (const float*)d_in[0];
    const float* w_off  = (const float*)d_in[1];
    const float* b_off  = (const float*)d_in[2];
    const float* weight = (const float*)d_in[3];
    const float* bias   = (const float*)d_in[4];
    const float* gamma  = (const float*)d_in[5];
    const float* beta   = (const float*)d_in[6];
    const float* rmean  = (const float*)d_in[7];
    const float* rvar   = (const float*)d_in[8];
    float* out = (float*)d_out;

    cudaFuncSetAttribute(gemm_mma_kernel,
                         cudaFuncAttributeMaxDynamicSharedMemorySize, GSM);

    wprep_kernel<<<(Oo * KTOT + 255) / 256, 256>>>(weight);

    offset_conv_part<<<Bb * 32 * CSPLIT, 128>>>(x, w_off);
    offset_reduce<<<(Bb * OCOFF * HW + 255) / 256, 256>>>(b_off);

    build_cols_kernel<<<NTOT / 32, 288>>>(x);

    {
        dim3 grid(NTOT / 128);
        gemm_mma_kernel<<<grid, 512, GSM>>>(bias, gamma, beta, rmean, rvar, out);
    }
}

// round 6
// speedup vs baseline: 3.7253x; 1.1748x over previous
#include <cuda_runtime.h>
#include <cuda_bf16.h>
#include <math.h>
#include <stdint.h>

#define Bb   8
#define Cc   256
#define Hh   64
#define Ww   64
#define Oo   256
#define HW   4096
#define OCOFF 27
#define KTOT 2304            /* bf16 elements of K (C*9) */
#define NTOT 32768           /* B*H*W */
#define CSPLIT 8
#define CPG (Cc / CSPLIT)

// ---------------- scratch (__device__ globals) ------------------------------
__device__ float    g_part[CSPLIT][Bb * OCOFF * HW];
__device__ float    g_om[Bb * OCOFF * HW];
__device__ uint16_t g_colsH[(size_t)KTOT * NTOT];   // bf16 hi plane, [k][n]
__device__ uint16_t g_colsL[(size_t)KTOT * NTOT];   // bf16 lo plane, [k][n]
__device__ uint16_t g_AH[Oo * KTOT];                // weight hi, [o][k]
__device__ uint16_t g_AL[Oo * KTOT];                // weight lo, [o][k]

// ---------------- helpers ----------------------------------------------------
__device__ __forceinline__ uint32_t smem_u32(const void* p) {
    uint32_t a;
    asm("{ .reg .u64 t; cvta.to.shared.u64 t, %1; cvt.u32.u64 %0, t; }" : "=r"(a) : "l"(p));
    return a;
}
__device__ __forceinline__ uint32_t swz(uint32_t off)  { return off ^ ((off >> 3) & 0x70); }
__device__ __forceinline__ uint32_t swz2(uint32_t off) { return off ^ ((off >> 4) & 0x70); }

__device__ __forceinline__ void cp16(uint32_t dst, const void* src) {
    asm volatile("cp.async.cg.shared.global [%0], [%1], 16;" :: "r"(dst), "l"(src));
}
#define CP_COMMIT() asm volatile("cp.async.commit_group;" ::: "memory")
#define CP_WAIT1()  asm volatile("cp.async.wait_group 1;" ::: "memory")

__device__ __forceinline__ void ldsm4(uint32_t* r, uint32_t addr) {
    asm volatile("ldmatrix.sync.aligned.m8n8.x4.shared.b16 {%0,%1,%2,%3}, [%4];"
                 : "=r"(r[0]), "=r"(r[1]), "=r"(r[2]), "=r"(r[3]) : "r"(addr));
}
__device__ __forceinline__ void ldsm4t(uint32_t* r, uint32_t addr) {
    asm volatile("ldmatrix.sync.aligned.m8n8.x4.trans.shared.b16 {%0,%1,%2,%3}, [%4];"
                 : "=r"(r[0]), "=r"(r[1]), "=r"(r[2]), "=r"(r[3]) : "r"(addr));
}
__device__ __forceinline__ void mma16816(float* c, const uint32_t* a,
                                         uint32_t b0, uint32_t b1) {
    asm volatile("mma.sync.aligned.m16n8k16.row.col.f32.bf16.bf16.f32 "
                 "{%0,%1,%2,%3}, {%4,%5,%6,%7}, {%8,%9}, {%0,%1,%2,%3};"
                 : "+f"(c[0]), "+f"(c[1]), "+f"(c[2]), "+f"(c[3])
                 : "r"(a[0]), "r"(a[1]), "r"(a[2]), "r"(a[3]), "r"(b0), "r"(b1));
}
__device__ __forceinline__ void fma2(unsigned long long& a, unsigned long long x,
                                     unsigned long long w) {
    asm("fma.rn.f32x2 %0, %1, %2, %0;" : "+l"(a) : "l"(x), "l"(w));
}
__device__ __forceinline__ unsigned long long pack2(float v) {
    unsigned long long r;
    asm("mov.b64 %0, {%1, %1};" : "=l"(r) : "r"(__float_as_uint(v)));
    return r;
}

// ===========================================================================
// Kernel A1: offset conv partials (32-ch groups), packed f32x2 math
// ===========================================================================
__global__ __launch_bounds__(128)
void offset_conv_part(const float* __restrict__ x,
                      const float* __restrict__ w_off) {
    __shared__ float sx[4][64];
    __shared__ __align__(16) float sw2[9 * 28];

    int cg = blockIdx.x & 7;
    int hs = (blockIdx.x >> 3) & 31;
    int b  = blockIdx.x >> 8;
    int h0 = hs << 1;
    int ty = threadIdx.x >> 6;
    int w  = threadIdx.x & 63;
    int h  = h0 + ty;

    if (threadIdx.x < 9) sw2[threadIdx.x * 28 + 27] = 0.f;

    unsigned long long acc2[14];
#pragma unroll
    for (int j = 0; j < 14; ++j) acc2[j] = 0ULL;

    const float* xb = x + (size_t)b * Cc * HW;
    int c0 = cg * CPG;

    for (int ci = 0; ci < CPG; ++ci) {
        int c = c0 + ci;
#pragma unroll
        for (int r = ty; r < 4; r += 2) {
            int yy = h0 - 1 + r;
            sx[r][w] = (yy >= 0 && yy < Hh) ? xb[(size_t)c * HW + yy * 64 + w] : 0.f;
        }
        for (int i = threadIdx.x; i < 243; i += 128) {
            int oc = i / 9, t = i - oc * 9;
            sw2[t * 28 + oc] = w_off[(size_t)oc * KTOT + c * 9 + t];
        }
        __syncthreads();

        float xv[9];
#pragma unroll
        for (int dy = 0; dy < 3; ++dy)
#pragma unroll
            for (int dx = 0; dx < 3; ++dx) {
                int xx = w - 1 + dx;
                xv[dy * 3 + dx] = (xx >= 0 && xx < Ww) ? sx[ty + dy][xx] : 0.f;
            }

#pragma unroll
        for (int t = 0; t < 9; ++t) {
            unsigned long long xp = pack2(xv[t]);
            const ulonglong2* wp = (const ulonglong2*)&sw2[t * 28];
#pragma unroll
            for (int j = 0; j < 7; ++j) {
                ulonglong2 w2 = wp[j];
                fma2(acc2[2 * j],     xp, w2.x);
                fma2(acc2[2 * j + 1], xp, w2.y);
            }
        }
        __syncthreads();
    }

    size_t outb = ((size_t)b * OCOFF) * HW + h * 64 + w;
#pragma unroll
    for (int j = 0; j < 14; ++j) {
        float lo = __uint_as_float((uint32_t)acc2[j]);
        float hi = __uint_as_float((uint32_t)(acc2[j] >> 32));
        int oc0 = 2 * j, oc1 = 2 * j + 1;
        g_part[cg][outb + (size_t)oc0 * HW] = lo;
        if (oc1 < OCOFF) g_part[cg][outb + (size_t)oc1 * HW] = hi;
    }
}

// ===========================================================================
// Kernel A2: reduce partials + bias + sigmoid(mask channels)
// ===========================================================================
__global__ void offset_reduce(const float* __restrict__ b_off) {
    int i = blockIdx.x * 256 + threadIdx.x;
    if (i >= Bb * OCOFF * HW) return;
    float s = 0.f;
#pragma unroll
    for (int g = 0; g < CSPLIT; ++g) s += g_part[g][i];
    int oc = (i >> 12) % OCOFF;
    s += b_off[oc];
    if (oc >= 18) s = 1.f / (1.f + expf(-s));
    g_om[i] = s;
}

// ===========================================================================
// Kernel W: split weights into bf16 hi (truncate) / lo (residual) planes
// ===========================================================================
__global__ void wprep_kernel(const float* __restrict__ weight) {
    int idx = blockIdx.x * 256 + threadIdx.x;
    if (idx >= Oo * KTOT) return;
    float wv = weight[idx];
    uint32_t vb = __float_as_uint(wv);
    uint32_t hb = vb & 0xFFFF0000u;
    float resid = wv - __uint_as_float(hb);
    g_AH[idx] = (uint16_t)(hb >> 16);
    g_AL[idx] = __bfloat16_as_ushort(__float2bfloat16_rn(resid));
}

// ===========================================================================
// Kernel B: deform-sample -> planar bf16 hi/lo cols in [k][n] layout.
// 288 threads = 32 n x 9 kk. Params in registers; loop 256 channels;
// DIRECT coalesced stores (warp lanes span n), no smem, no barriers.
// ===========================================================================
__global__ __launch_bounds__(288)
void build_cols_kernel(const float* __restrict__ x) {
    int tid = threadIdx.x;
    int n_l = tid & 31;
    int kk  = tid >> 5;                // 0..8
    int n0  = blockIdx.x * 32;
    int n   = n0 + n_l;
    int b   = n >> 12;
    int hw  = n & 4095;
    int h   = hw >> 6, w = hw & 63;

    const float* omb = g_om + (size_t)b * OCOFF * HW;
    float oy = omb[(size_t)kk * HW + hw];
    float ox = omb[(size_t)(9 + kk) * HW + hw];
    float m  = omb[(size_t)(18 + kk) * HW + hw];

    float py = (float)(h - 1 + kk / 3) + oy;
    float px = (float)(w - 1 + kk % 3) + ox;
    float y0f = floorf(py), x0f = floorf(px);
    float wy = py - y0f, wx = px - x0f;
    int y0 = (int)y0f, x0 = (int)x0f;

    bool yv0 = (y0 >= 0) & (y0 < Hh);
    bool yv1 = (y0 + 1 >= 0) & (y0 + 1 < Hh);
    bool xv0 = (x0 >= 0) & (x0 < Ww);
    bool xv1 = (x0 + 1 >= 0) & (x0 + 1 < Ww);

    float w00 = m * (1.f - wy) * (1.f - wx) * (float)(yv0 & xv0);
    float w01 = m * (1.f - wy) * wx         * (float)(yv0 & xv1);
    float w10 = m * wy * (1.f - wx)         * (float)(yv1 & xv0);
    float w11 = m * wy * wx                 * (float)(yv1 & xv1);

    int y0c = min(max(y0, 0), Hh - 1);
    int y1c = min(max(y0 + 1, 0), Hh - 1);
    int x0c = min(max(x0, 0), Ww - 1);
    int x1c = min(max(x0 + 1, 0), Ww - 1);
    int o00 = y0c * 64 + x0c, o01 = y0c * 64 + x1c;
    int o10 = y1c * 64 + x0c, o11 = y1c * 64 + x1c;

    const float* xb = x + (size_t)b * Cc * HW;

#pragma unroll 1
    for (int c0 = 0; c0 < Cc; c0 += 8) {
        float val[8];
#pragma unroll
        for (int cl = 0; cl < 8; ++cl) {
            const float* xc = xb + (size_t)(c0 + cl) * HW;
            val[cl] = xc[o00] * w00 + xc[o01] * w01
                    + xc[o10] * w10 + xc[o11] * w11;
        }
#pragma unroll
        for (int cl = 0; cl < 8; ++cl) {
            uint32_t vb = __float_as_uint(val[cl]);
            uint32_t hb = vb & 0xFFFF0000u;
            float resid = val[cl] - __uint_as_float(hb);
            uint16_t lb = __bfloat16_as_ushort(__float2bfloat16_rn(resid));
            size_t off = (size_t)((c0 + cl) * 9 + kk) * NTOT + n;
            g_colsH[off] = (uint16_t)(hb >> 16);
            g_colsL[off] = lb;
        }
    }
}

// ===========================================================================
// Kernel C: HMMA 3-term bf16 GEMM.  M=256 x N=128 tiles, K=2304 per chain.
// out = AH*BH + AL*BH + AH*BL   (AL*BL dropped, ~2^-16)
// B stored [k][n]; B tile 64 k-rows x 256B; ldmatrix.trans.
// ===========================================================================
#define AT 32768                 /* 256 rows x 128B */
#define BT 16384                 /* 64 k-rows x 256B */
#define STAGEB (2 * AT + 2 * BT) /* 98304 */
#define GSM    (2 * STAGEB)      /* 196608 */
#define NCHUNK 36

__device__ __forceinline__ void load_chunk(uint32_t sbu, int st, int chunk,
                                           int bn, int tid) {
    int kw = chunk * 64;
    uint32_t base = sbu + st * STAGEB;
    int r = tid >> 3, q = tid & 7;
    // A: 256 rows x 128B per plane
#pragma unroll
    for (int rr = 0; rr < 4; ++rr) {
        int row = r + rr * 64;
        uint32_t o = swz((uint32_t)(row * 128 + q * 16));
        cp16(base + o,      &g_AH[(size_t)row * KTOT + kw + q * 8]);
        cp16(base + AT + o, &g_AL[(size_t)row * KTOT + kw + q * 8]);
    }
    // B: 64 k-rows x 256B per plane (n-contiguous)
    {
        int krow = tid >> 3;          // 0..63
        uint32_t o0 = swz2((uint32_t)(krow * 256 + q * 16));
        uint32_t o1 = swz2((uint32_t)(krow * 256 + (q + 8) * 16));
        const uint16_t* sH = &g_colsH[(size_t)(kw + krow) * NTOT + bn];
        const uint16_t* sL = &g_colsL[(size_t)(kw + krow) * NTOT + bn];
        cp16(base + 2 * AT + o0,      sH + q * 8);
        cp16(base + 2 * AT + o1,      sH + (q + 8) * 8);
        cp16(base + 2 * AT + BT + o0, sL + q * 8);
        cp16(base + 2 * AT + BT + o1, sL + (q + 8) * 8);
    }
}

__global__ __launch_bounds__(512, 1)
void gemm_mma_kernel(const float* __restrict__ bias,
                     const float* __restrict__ gamma,
                     const float* __restrict__ beta,
                     const float* __restrict__ rmean,
                     const float* __restrict__ rvar,
                     float* __restrict__ out) {
    extern __shared__ char smc[];
    uint32_t sbu = smem_u32(smc);
    int tid  = threadIdx.x;
    int lane = tid & 31;
    int wid  = tid >> 5;
    int bn = blockIdx.x * 128;
    int warp_m = wid & 7;
    int warp_n = wid >> 3;

    // A-side ldmatrix lane pieces (row-major, 128B rows)
    int mi   = lane >> 3;
    int mrow = lane & 7;
    int rbit = ((mi & 1) << 3) + mrow;
    int cbit = (mi >> 1) << 4;
    // B-side ldmatrix.trans lane pieces (k-major, 256B rows)
    int klane = ((mi >> 1) << 3) + mrow;   // 0..15
    int nlane = (mi & 1) << 3;             // 0 or 8

    float acc[2][8][4];
#pragma unroll
    for (int a = 0; a < 2; ++a)
#pragma unroll
        for (int b2 = 0; b2 < 8; ++b2)
#pragma unroll
            for (int c2 = 0; c2 < 4; ++c2) acc[a][b2][c2] = 0.f;

    load_chunk(sbu, 0, 0, bn, tid); CP_COMMIT();
    load_chunk(sbu, 1, 1, bn, tid); CP_COMMIT();

    int arow0 = warp_m * 32;
    int brow0 = warp_n * 64;

    for (int i = 0; i < NCHUNK; ++i) {
        int st = i & 1;
        CP_WAIT1();
        __syncthreads();

        uint32_t base = sbu + st * STAGEB;
#pragma unroll
        for (int ks = 0; ks < 4; ++ks) {
            int kb = ks * 32;                  // byte offset in A rows
            uint32_t boffs[4], aoffs[2];
#pragma unroll
            for (int ng = 0; ng < 4; ++ng)
                boffs[ng] = swz2((uint32_t)((ks * 16 + klane) * 256
                                 + (brow0 + ng * 16 + nlane) * 2));
#pragma unroll
            for (int mt = 0; mt < 2; ++mt)
                aoffs[mt] = swz((uint32_t)((arow0 + mt * 16 + rbit) * 128 + kb + cbit));

            uint32_t bq[4][4], ah[2][4];
#pragma unroll
            for (int ng = 0; ng < 4; ++ng) ldsm4t(bq[ng], base + 2 * AT + boffs[ng]);
#pragma unroll
            for (int mt = 0; mt < 2; ++mt) ldsm4(ah[mt], base + aoffs[mt]);

            // AH x BH
#pragma unroll
            for (int mt = 0; mt < 2; ++mt)
#pragma unroll
                for (int ng = 0; ng < 4; ++ng) {
                    mma16816(acc[mt][ng * 2 + 0], ah[mt], bq[ng][0], bq[ng][2]);
                    mma16816(acc[mt][ng * 2 + 1], ah[mt], bq[ng][1], bq[ng][3]);
                }
            // AL x BH
#pragma unroll
            for (int mt = 0; mt < 2; ++mt) {
                uint32_t al[4];
                ldsm4(al, base + AT + aoffs[mt]);
#pragma unroll
                for (int ng = 0; ng < 4; ++ng) {
                    mma16816(acc[mt][ng * 2 + 0], al, bq[ng][0], bq[ng][2]);
                    mma16816(acc[mt][ng * 2 + 1], al, bq[ng][1], bq[ng][3]);
                }
            }
            // AH x BL (reuse bq regs)
#pragma unroll
            for (int ng = 0; ng < 4; ++ng) ldsm4t(bq[ng], base + 2 * AT + BT + boffs[ng]);
#pragma unroll
            for (int mt = 0; mt < 2; ++mt)
#pragma unroll
                for (int ng = 0; ng < 4; ++ng) {
                    mma16816(acc[mt][ng * 2 + 0], ah[mt], bq[ng][0], bq[ng][2]);
                    mma16816(acc[mt][ng * 2 + 1], ah[mt], bq[ng][1], bq[ng][3]);
                }
        }
        __syncthreads();
        if (i + 2 < NCHUNK) load_chunk(sbu, st, i + 2, bn, tid);
        CP_COMMIT();
    }

    // epilogue: BN + bias + ReLU, float2 stores
    int nbase = bn + warp_n * 64;
#pragma unroll
    for (int mt = 0; mt < 2; ++mt) {
        int o0 = warp_m * 32 + mt * 16 + (lane >> 2);
        int o1 = o0 + 8;
        float inv0 = gamma[o0] * rsqrtf(rvar[o0] + 1e-5f);
        float sh0  = beta[o0] - rmean[o0] * inv0 + bias[o0] * inv0;
        float inv1 = gamma[o1] * rsqrtf(rvar[o1] + 1e-5f);
        float sh1  = beta[o1] - rmean[o1] * inv1 + bias[o1] * inv1;
#pragma unroll
        for (int nt = 0; nt < 8; ++nt) {
            int n = nbase + nt * 8 + ((lane & 3) << 1);
            int bimg = n >> 12;
            int hw   = n & 4095;
            float2 v0, v1;
            v0.x = fmaxf(fmaf(acc[mt][nt][0], inv0, sh0), 0.f);
            v0.y = fmaxf(fmaf(acc[mt][nt][1], inv0, sh0), 0.f);
            v1.x = fmaxf(fmaf(acc[mt][nt][2], inv1, sh1), 0.f);
            v1.y = fmaxf(fmaf(acc[mt][nt][3], inv1, sh1), 0.f);
            *(float2*)&out[(((size_t)(bimg * Oo + o0)) << 12) + hw] = v0;
            *(float2*)&out[(((size_t)(bimg * Oo + o1)) << 12) + hw] = v1;
        }
    }
}

// ===========================================================================
extern "C" void kernel_launch(void* const* d_in, const int* in_sizes, int n_in,
                              void* d_out, int out_size) {
    const float* x      = (const float*)d_in[0];
    const float* w_off  = (const float*)d_in[1];
    const float* b_off  = (const float*)d_in[2];
    const float* weight = (const float*)d_in[3];
    const float* bias   = (const float*)d_in[4];
    const float* gamma  = (const float*)d_in[5];
    const float* beta   = (const float*)d_in[6];
    const float* rmean  = (const float*)d_in[7];
    const float* rvar   = (const float*)d_in[8];
    float* out = (float*)d_out;

    cudaFuncSetAttribute(gemm_mma_kernel,
                         cudaFuncAttributeMaxDynamicSharedMemorySize, GSM);

    wprep_kernel<<<(Oo * KTOT + 255) / 256, 256>>>(weight);

    offset_conv_part<<<Bb * 32 * CSPLIT, 128>>>(x, w_off);
    offset_reduce<<<(Bb * OCOFF * HW + 255) / 256, 256>>>(b_off);

    build_cols_kernel<<<NTOT / 32, 288>>>(x);

    {
        dim3 grid(NTOT / 128);
        gemm_mma_kernel<<<grid, 512, GSM>>>(bias, gamma, beta, rmean, rvar, out);
    }
}